// round 2
// baseline (speedup 1.0000x reference)
#include <cuda_runtime.h>

#define HW (512 * 512)
#define EPS 1e-6f

__global__ __launch_bounds__(256) void Interpolate_28664611734214_kernel(
    const float* __restrict__ data,      // (9,9,512,512,3)
    const float* __restrict__ cam_xyz,   // (3,)
    const int*   __restrict__ neighbors, // (4,2)
    const int*   __restrict__ uv,        // (4,512,512,2)
    float*       __restrict__ out)       // flat (HW,3) reinterpreted as (3,512,512)
{
    const int pix = blockIdx.x * blockDim.x + threadIdx.x;
    if (pix >= HW) return;

    // ---- weights (tiny, recomputed per-thread; all loads L1-broadcast) ----
    const float c0 = __ldg(cam_xyz + 0);
    const float c1 = __ldg(cam_xyz + 1);

    int n0[4], n1[4];
    float t[4];
#pragma unroll
    for (int j = 0; j < 4; j++) {
        n0[j] = __ldg(neighbors + 2 * j + 0);
        n1[j] = __ldg(neighbors + 2 * j + 1);
        const float d0 = c0 - (float)n0[j];
        const float d1 = c1 - (float)n1[j];
        float v = fabsf(d0 * d1);
        t[j] = (v <= EPS) ? 0.0f : v;   // threshold BEFORE sum (matches ref)
    }
    const float s = t[0] + t[1] + t[2] + t[3];

    float w[4];
#pragma unroll
    for (int n = 0; n < 4; n++) {
        // flip: weight for gathered[n] comes from t of neighbor (3-n)
        const float x = t[3 - n] / s;
        w[n] = (fabsf(x) <= EPS) ? 0.0f : x;
    }

    // ---- gather + weighted sum; full unroll -> all loads front-batched ----
    float r = 0.0f, g = 0.0f, b = 0.0f;
#pragma unroll
    for (int n = 0; n < 4; n++) {
        const int2 q = __ldg((const int2*)uv + n * HW + pix);  // (u, v)
        // data index: (((s*9 + t)*512 + u)*512 + v)*3  — fits in int32 (<64M)
        const int idx = (((n0[n] * 9 + n1[n]) * 512 + q.x) * 512 + q.y) * 3;
        const float wn = w[n];
        r += wn * __ldg(data + idx + 0);
        g += wn * __ldg(data + idx + 1);
        b += wn * __ldg(data + idx + 2);
    }

    // einsum result is (HW, 3) then reinterpreted as (3,H,W): interleaved layout
    out[3 * pix + 0] = r;
    out[3 * pix + 1] = g;
    out[3 * pix + 2] = b;
}

extern "C" void kernel_launch(void* const* d_in, const int* in_sizes, int n_in,
                              void* d_out, int out_size) {
    // metadata order: data, pixel, cam_xyz, neighbors, uv
    const float* data      = (const float*)d_in[0];
    // d_in[1] = pixel, only its shape is used by the reference -> unused here
    const float* cam_xyz   = (const float*)d_in[2];
    const int*   neighbors = (const int*)d_in[3];
    const int*   uv        = (const int*)d_in[4];
    float*       out       = (float*)d_out;

    const int threads = 256;
    const int blocks  = (HW + threads - 1) / threads;  // 1024
    Interpolate_28664611734214_kernel<<<blocks, threads>>>(
        data, cam_xyz, neighbors, uv, out);
}